// round 7
// baseline (speedup 1.0000x reference)
#include <cuda_runtime.h>
#include <cstdint>

// out[m][d] = sum_k ecg[m*128+k] * W[d*128+k] + b[d],  M=196608, K=128, N=64.
// bf16-split HMMA (mma.sync.m16n8k16): D = Ahi*Whi + Alo*Whi + Ahi*Wlo.
// Persistent CTAs: W split once per block, tiles looped with no per-tile barrier.

#define THREADS 128
#define BM 128
#define NBLK 444   // 148 SMs x 3 CTAs
#define WPAD 136   // bf16 per padded W row (272 B rows -> conflict-free ldmatrix)

__device__ __forceinline__ uint32_t s2u(const void* p) {
    uint32_t a;
    asm("{ .reg .u64 t; cvta.to.shared.u64 t, %1; cvt.u32.u64 %0, t; }" : "=r"(a) : "l"(p));
    return a;
}

__device__ __forceinline__ void split2(float x, float y, uint32_t& hi, uint32_t& lo) {
    asm("cvt.rn.bf16x2.f32 %0, %1, %2;" : "=r"(hi) : "f"(y), "f"(x));
    float hx = __uint_as_float(hi << 16);
    float hy = __uint_as_float(hi & 0xffff0000u);
    float lx = x - hx, ly = y - hy;
    asm("cvt.rn.bf16x2.f32 %0, %1, %2;" : "=r"(lo) : "f"(ly), "f"(lx));
}

__device__ __forceinline__ void ldsm4(uint32_t& r0, uint32_t& r1, uint32_t& r2,
                                      uint32_t& r3, uint32_t addr) {
    asm volatile("ldmatrix.sync.aligned.m8n8.x4.shared.b16 {%0,%1,%2,%3}, [%4];"
                 : "=r"(r0), "=r"(r1), "=r"(r2), "=r"(r3) : "r"(addr));
}

__device__ __forceinline__ void mma16816(float* c,
                                         uint32_t a0, uint32_t a1, uint32_t a2, uint32_t a3,
                                         uint32_t b0, uint32_t b1) {
    asm volatile(
        "mma.sync.aligned.m16n8k16.row.col.f32.bf16.bf16.f32 "
        "{%0,%1,%2,%3}, {%4,%5,%6,%7}, {%8,%9}, {%0,%1,%2,%3};"
        : "+f"(c[0]), "+f"(c[1]), "+f"(c[2]), "+f"(c[3])
        : "r"(a0), "r"(a1), "r"(a2), "r"(a3), "r"(b0), "r"(b1));
}

__global__ __launch_bounds__(THREADS, 3)
void ecg_tok_mma(const float* __restrict__ ecg,
                 const float* __restrict__ W,
                 const float* __restrict__ bias,
                 float* __restrict__ out,
                 int numTiles, long long xelems, int fillCount) {
    __shared__ __align__(16) uint32_t Whi32[64 * WPAD / 2];
    __shared__ __align__(16) uint32_t Wlo32[64 * WPAD / 2];

    const int tid  = threadIdx.x;
    const int warp = tid >> 5;
    const int lane = tid & 31;

    // ---- folded fill: beat_intervals tail ----
    {
        int fi = blockIdx.x * THREADS + tid;
        if (fi < fillCount) out[xelems + fi] = 128.0f;
    }

    // ---- once per block: load + split W with per-16-chunk column permutation ----
    // global pair g of a chunk -> slice pair (g>>1) + (g&1)*4 (same perm applied to A).
    #pragma unroll
    for (int it = 0; it < 16; it++) {
        int idx   = tid + it * THREADS;     // 0..2047
        int n     = idx >> 5;
        int r     = idx & 31;
        int chunk = r >> 2;
        int q     = r & 3;
        float4 v = *reinterpret_cast<const float4*>(W + n * 128 + chunk * 16 + q * 4);
        uint32_t h0, l0, h1, l1;
        split2(v.x, v.y, h0, l0);
        split2(v.z, v.w, h1, l1);
        int u = n * (WPAD / 2) + chunk * 8 + q;
        Whi32[u]     = h0;
        Whi32[u + 4] = h1;
        Wlo32[u]     = l0;
        Wlo32[u + 4] = l1;
    }
    __syncthreads();

    // ldmatrix lane addressing
    const int lm_row  = ((lane >> 4) << 3) + (lane & 7);
    const int lm_kofs = ((lane >> 3) & 1) << 4;   // bytes
    const uint32_t lm_term  = (uint32_t)(lm_row * (WPAD * 2) + lm_kofs);
    const uint32_t whi_base = s2u(Whi32) + lm_term;
    const uint32_t wlo_base = s2u(Wlo32) + lm_term;

    // per-thread geometry (tile-independent parts)
    const int arow  = warp * 32 + (lane >> 2);
    const int acol4 = 4 * (lane & 3);
    const int ncol  = 2 * (lane & 3);

    // ---- persistent tile loop (no barriers inside) ----
    for (int t = blockIdx.x; t < numTiles; t += NBLK) {
        const long long m0 = (long long)t * BM;
        const float* abase = ecg + (m0 + arow) * 128 + acol4;

        float acc[2][8][4];
        #pragma unroll
        for (int f = 0; f < 2; f++)
            #pragma unroll
            for (int nt = 0; nt < 8; nt++)
                #pragma unroll
                for (int j = 0; j < 4; j++) acc[f][nt][j] = 0.0f;

        float4 cur[4];
        #pragma unroll
        for (int j = 0; j < 4; j++)
            cur[j] = *reinterpret_cast<const float4*>(abase + j * 8 * 128);

        #pragma unroll
        for (int s = 0; s < 8; s++) {
            uint32_t ah[8], al[8];
            #pragma unroll
            for (int j = 0; j < 4; j++) {
                split2(cur[j].x, cur[j].y, ah[2 * j],     al[2 * j]);
                split2(cur[j].z, cur[j].w, ah[2 * j + 1], al[2 * j + 1]);
            }

            if (s < 7) {
                #pragma unroll
                for (int j = 0; j < 4; j++)
                    cur[j] = *reinterpret_cast<const float4*>(
                        abase + (s + 1) * 16 + j * 8 * 128);
            }

            #pragma unroll
            for (int ntp = 0; ntp < 4; ntp++) {
                uint32_t off = (uint32_t)(ntp * 16 * WPAD * 2 + s * 32);
                uint32_t bh0, bh1, bh2, bh3, bl0, bl1, bl2, bl3;
                ldsm4(bh0, bh1, bh2, bh3, whi_base + off);
                ldsm4(bl0, bl1, bl2, bl3, wlo_base + off);

                #pragma unroll
                for (int f = 0; f < 2; f++) {
                    float* c0 = acc[f][2 * ntp];
                    float* c1 = acc[f][2 * ntp + 1];
                    mma16816(c0, ah[4*f], ah[4*f+2], ah[4*f+1], ah[4*f+3], bh0, bh1);
                    mma16816(c1, ah[4*f], ah[4*f+2], ah[4*f+1], ah[4*f+3], bh2, bh3);
                    mma16816(c0, al[4*f], al[4*f+2], al[4*f+1], al[4*f+3], bh0, bh1);
                    mma16816(c1, al[4*f], al[4*f+2], al[4*f+1], al[4*f+3], bh2, bh3);
                    mma16816(c0, ah[4*f], ah[4*f+2], ah[4*f+1], ah[4*f+3], bl0, bl1);
                    mma16816(c1, ah[4*f], ah[4*f+2], ah[4*f+1], ah[4*f+3], bl2, bl3);
                }
            }
        }

        // epilogue: add bias, store (overlaps next tile's loads; no barrier)
        #pragma unroll
        for (int f = 0; f < 2; f++) {
            long long row0 = m0 + warp * 32 + f * 16 + (lane >> 2);
            float* orow0 = out + row0 * 64;
            float* orow1 = orow0 + 8 * 64;
            #pragma unroll
            for (int nt = 0; nt < 8; nt++) {
                float2 bv = *reinterpret_cast<const float2*>(bias + nt * 8 + ncol);
                float2 o0, o1;
                o0.x = acc[f][nt][0] + bv.x;  o0.y = acc[f][nt][1] + bv.y;
                o1.x = acc[f][nt][2] + bv.x;  o1.y = acc[f][nt][3] + bv.y;
                *reinterpret_cast<float2*>(orow0 + nt * 8 + ncol) = o0;
                *reinterpret_cast<float2*>(orow1 + nt * 8 + ncol) = o1;
            }
        }
    }
}

extern "C" void kernel_launch(void* const* d_in, const int* in_sizes, int n_in,
                              void* d_out, int out_size) {
    const float* ecg = (const float*)d_in[0];
    const float* W   = (const float*)d_in[1];
    const float* b   = (const float*)d_in[2];
    float* out = (float*)d_out;

    const int M = in_sizes[0] / 128;
    const int numTiles = M / BM;                 // 1536
    const long long xelems = (long long)M * 64;
    const int fillCount = out_size - (int)xelems;

    ecg_tok_mma<<<NBLK, THREADS>>>(ecg, W, b, out, numTiles, xelems, fillCount);
}